// round 1
// baseline (speedup 1.0000x reference)
#include <cuda_runtime.h>
#include <cstddef>

// ---------------- problem constants ----------------
#define B_  32
#define L_  512
#define E_  768
#define F_  512
#define M_  (B_ * L_)          // 16384 rows
#define EPSF 1e-7f

// ---------------- d_out layout (floats) ----------------
#define OFF_APRED 0L
#define OFF_OPRED 49152L
#define OFF_SPRED 98304L
#define OFF_AINT  147456L      // [B,L,1024]
#define OFF_OINT  16924672L    // [B,L,1024]
#define OFF_CINT  33701888L    // [B,L,768]
#define OFF_CCONV 46284800L    // [B,L,768]

// ---------------- device scratch ----------------
__device__ float g_aconv[(size_t)M_ * F_];            // 32 MB
__device__ float g_oconv[(size_t)M_ * F_];            // 32 MB
__device__ float g_G [(size_t)B_ * L_ * L_];          // 32 MB (gram / expG, reused as WS0)
__device__ float g_A1[(size_t)B_ * L_ * L_];          // 32 MB
__device__ float g_A2[(size_t)B_ * L_ * L_];          // 32 MB (reused as WS / word_attend)
__device__ float g_inva[M_], g_invo[M_], g_invc[M_];
__device__ float g_rowsum[M_], g_colsum[M_], g_colsumP[M_];
__device__ float g_msum[B_];
__device__ float g_conf[M_];

// =====================================================================
// Conv1d(K=3, SAME) + bias + relu as GEMM:  [M x 2304] @ [2304 x N]
// A is gathered from x with per-tap shift; 768 % 8 == 0 so a BK=8 tile
// never crosses a tap boundary.
// =====================================================================
__global__ __launch_bounds__(256) void conv_gemm(
    const float* __restrict__ X, const float* __restrict__ W,
    const float* __restrict__ bias,
    float* __restrict__ C1, int ldc1,
    float* __restrict__ C2, int ldc2, int N)
{
    __shared__ float As[8 * 128];
    __shared__ float Bs[8 * 128];
    const int tid = threadIdx.x;
    const int tx = tid & 15, ty = tid >> 4;
    const int m0 = blockIdx.x * 128;
    const int n0 = blockIdx.y * 128;

    const int arow  = tid >> 1;
    const int ahalf = (tid & 1) * 4;
    const int gm_a  = m0 + arow;
    const int b = gm_a >> 9, l = gm_a & 511;

    const int brow = tid >> 5;
    const int bcol = (tid & 31) * 4;

    float acc[8][8];
#pragma unroll
    for (int i = 0; i < 8; i++)
#pragma unroll
        for (int j = 0; j < 8; j++) acc[i][j] = 0.f;

    for (int kt = 0; kt < 288; ++kt) {
        const int k0  = kt * 8;
        const int tap = k0 / 768;
        const int e0  = k0 - tap * 768;
        const int src = l + tap - 1;

        float4 av = make_float4(0.f, 0.f, 0.f, 0.f);
        if (src >= 0 && src < L_)
            av = *reinterpret_cast<const float4*>(
                X + ((size_t)(b * L_ + src)) * E_ + e0 + ahalf);
        float4 bv = *reinterpret_cast<const float4*>(
            W + ((size_t)(k0 + brow)) * N + n0 + bcol);

        __syncthreads();
        As[(ahalf + 0) * 128 + arow] = av.x;
        As[(ahalf + 1) * 128 + arow] = av.y;
        As[(ahalf + 2) * 128 + arow] = av.z;
        As[(ahalf + 3) * 128 + arow] = av.w;
        *reinterpret_cast<float4*>(Bs + brow * 128 + bcol) = bv;
        __syncthreads();

#pragma unroll
        for (int k = 0; k < 8; k++) {
            float a[8], bb[8];
            *reinterpret_cast<float4*>(a)     = *reinterpret_cast<const float4*>(As + k * 128 + ty * 8);
            *reinterpret_cast<float4*>(a + 4) = *reinterpret_cast<const float4*>(As + k * 128 + ty * 8 + 4);
            *reinterpret_cast<float4*>(bb)     = *reinterpret_cast<const float4*>(Bs + k * 128 + tx * 8);
            *reinterpret_cast<float4*>(bb + 4) = *reinterpret_cast<const float4*>(Bs + k * 128 + tx * 8 + 4);
#pragma unroll
            for (int i = 0; i < 8; i++)
#pragma unroll
                for (int j = 0; j < 8; j++)
                    acc[i][j] = fmaf(a[i], bb[j], acc[i][j]);
        }
    }

#pragma unroll
    for (int i = 0; i < 8; i++) {
        const int gm = m0 + ty * 8 + i;
#pragma unroll
        for (int j = 0; j < 8; j++) {
            const int gn = n0 + tx * 8 + j;
            float v = fmaxf(acc[i][j] + bias[gn], 0.f);
            C1[(size_t)gm * ldc1 + gn] = v;
            if (C2) C2[(size_t)gm * ldc2 + gn] = v;
        }
    }
}

// =====================================================================
// Batched NT GEMM: C[b,i,j] = (A[b,i,:] . Bv[b,j,:]) * rs[b,i] * cs[b,j]
// A,Bv: [B,512,K] row-major. C: [B,512,512]. rs/cs nullable.
// =====================================================================
__global__ __launch_bounds__(256) void gemm_nt(
    const float* __restrict__ Aa, const float* __restrict__ Bv,
    float* __restrict__ C,
    const float* __restrict__ rs, const float* __restrict__ cs, int K)
{
    __shared__ float As[8 * 128];
    __shared__ float Bs[8 * 128];
    const int tid = threadIdx.x;
    const int tx = tid & 15, ty = tid >> 4;
    const int bz = blockIdx.z;
    const int m0 = blockIdx.x * 128, n0 = blockIdx.y * 128;
    const float* Ab = Aa + (size_t)bz * L_ * K;
    const float* Bb = Bv + (size_t)bz * L_ * K;

    const int arow  = tid >> 1;
    const int ahalf = (tid & 1) * 4;

    float acc[8][8];
#pragma unroll
    for (int i = 0; i < 8; i++)
#pragma unroll
        for (int j = 0; j < 8; j++) acc[i][j] = 0.f;

    for (int k0 = 0; k0 < K; k0 += 8) {
        float4 av = *reinterpret_cast<const float4*>(Ab + (size_t)(m0 + arow) * K + k0 + ahalf);
        float4 bv = *reinterpret_cast<const float4*>(Bb + (size_t)(n0 + arow) * K + k0 + ahalf);
        __syncthreads();
        As[(ahalf + 0) * 128 + arow] = av.x;
        As[(ahalf + 1) * 128 + arow] = av.y;
        As[(ahalf + 2) * 128 + arow] = av.z;
        As[(ahalf + 3) * 128 + arow] = av.w;
        Bs[(ahalf + 0) * 128 + arow] = bv.x;
        Bs[(ahalf + 1) * 128 + arow] = bv.y;
        Bs[(ahalf + 2) * 128 + arow] = bv.z;
        Bs[(ahalf + 3) * 128 + arow] = bv.w;
        __syncthreads();
#pragma unroll
        for (int k = 0; k < 8; k++) {
            float a[8], bb[8];
            *reinterpret_cast<float4*>(a)     = *reinterpret_cast<const float4*>(As + k * 128 + ty * 8);
            *reinterpret_cast<float4*>(a + 4) = *reinterpret_cast<const float4*>(As + k * 128 + ty * 8 + 4);
            *reinterpret_cast<float4*>(bb)     = *reinterpret_cast<const float4*>(Bs + k * 128 + tx * 8);
            *reinterpret_cast<float4*>(bb + 4) = *reinterpret_cast<const float4*>(Bs + k * 128 + tx * 8 + 4);
#pragma unroll
            for (int i = 0; i < 8; i++)
#pragma unroll
                for (int j = 0; j < 8; j++)
                    acc[i][j] = fmaf(a[i], bb[j], acc[i][j]);
        }
    }

#pragma unroll
    for (int i = 0; i < 8; i++) {
        const int mi = m0 + ty * 8 + i;
        const float rsc = rs ? rs[bz * L_ + mi] : 1.f;
#pragma unroll
        for (int j = 0; j < 8; j++) {
            const int nj = n0 + tx * 8 + j;
            const float csc = cs ? cs[bz * L_ + nj] : 1.f;
            C[(size_t)bz * L_ * L_ + (size_t)mi * L_ + nj] = acc[i][j] * rsc * csc;
        }
    }
}

// =====================================================================
// Batched NN GEMM: C[(b*512+i)*ldc + n] = A[b,i,:] @ Bm[b,:,n] (+ add row)
// A: [B,512,K], Bm: [B,K,N]. C base may include a column offset.
// =====================================================================
__global__ __launch_bounds__(256) void gemm_nn(
    const float* __restrict__ Aa, const float* __restrict__ Bm,
    float* __restrict__ C, const float* __restrict__ addp,
    int K, int N, int ldc)
{
    __shared__ float As[8 * 128];
    __shared__ float Bs[8 * 128];
    const int tid = threadIdx.x;
    const int tx = tid & 15, ty = tid >> 4;
    const int bz = blockIdx.z;
    const int m0 = blockIdx.x * 128, n0 = blockIdx.y * 128;
    const float* Ab = Aa + (size_t)bz * L_ * K;
    const float* Bb = Bm + (size_t)bz * K * N;

    const int arow  = tid >> 1;
    const int ahalf = (tid & 1) * 4;
    const int brow = tid >> 5;
    const int bcol = (tid & 31) * 4;

    float acc[8][8];
#pragma unroll
    for (int i = 0; i < 8; i++)
#pragma unroll
        for (int j = 0; j < 8; j++) acc[i][j] = 0.f;

    for (int k0 = 0; k0 < K; k0 += 8) {
        float4 av = *reinterpret_cast<const float4*>(Ab + (size_t)(m0 + arow) * K + k0 + ahalf);
        float4 bv = *reinterpret_cast<const float4*>(Bb + (size_t)(k0 + brow) * N + n0 + bcol);
        __syncthreads();
        As[(ahalf + 0) * 128 + arow] = av.x;
        As[(ahalf + 1) * 128 + arow] = av.y;
        As[(ahalf + 2) * 128 + arow] = av.z;
        As[(ahalf + 3) * 128 + arow] = av.w;
        *reinterpret_cast<float4*>(Bs + brow * 128 + bcol) = bv;
        __syncthreads();
#pragma unroll
        for (int k = 0; k < 8; k++) {
            float a[8], bb[8];
            *reinterpret_cast<float4*>(a)     = *reinterpret_cast<const float4*>(As + k * 128 + ty * 8);
            *reinterpret_cast<float4*>(a + 4) = *reinterpret_cast<const float4*>(As + k * 128 + ty * 8 + 4);
            *reinterpret_cast<float4*>(bb)     = *reinterpret_cast<const float4*>(Bs + k * 128 + tx * 8);
            *reinterpret_cast<float4*>(bb + 4) = *reinterpret_cast<const float4*>(Bs + k * 128 + tx * 8 + 4);
#pragma unroll
            for (int i = 0; i < 8; i++)
#pragma unroll
                for (int j = 0; j < 8; j++)
                    acc[i][j] = fmaf(a[i], bb[j], acc[i][j]);
        }
    }

#pragma unroll
    for (int i = 0; i < 8; i++) {
        const size_t grow = (size_t)bz * L_ + m0 + ty * 8 + i;
#pragma unroll
        for (int j = 0; j < 8; j++) {
            const int nj = n0 + tx * 8 + j;
            float v = acc[i][j];
            if (addp) v += addp[grow * N + nj];
            C[grow * ldc + nj] = v;
        }
    }
}

// ---------------- row inverse l2 norm ----------------
__global__ void rowinv_k(const float* __restrict__ X, int D, float* __restrict__ inv)
{
    const int m = blockIdx.x, t = threadIdx.x;   // 256 threads
    float s = 0.f;
    for (int k = t; k < D; k += 256) { float v = X[(size_t)m * D + k]; s = fmaf(v, v, s); }
    __shared__ float red[256];
    red[t] = s; __syncthreads();
    for (int st = 128; st > 0; st >>= 1) { if (t < st) red[t] += red[t + st]; __syncthreads(); }
    if (t == 0) inv[m] = rsqrtf(fmaxf(red[0], 1e-12f));
}

// ---------------- exp(G) in place + masked row sums ----------------
__global__ void exp_rowsum_k(const float* __restrict__ mask)
{
    const int row = blockIdx.x, t = threadIdx.x;  // 512 threads
    const int b = row >> 9;
    const size_t idx = (size_t)row * L_ + t;
    float e = expf(g_G[idx]);
    g_G[idx] = e;
    float v = e * mask[b * L_ + t];
    __shared__ float red[512];
    red[t] = v; __syncthreads();
    for (int st = 256; st > 0; st >>= 1) { if (t < st) red[t] += red[t + st]; __syncthreads(); }
    if (t == 0) g_rowsum[row] = red[0];
}

// ---------------- deterministic column sums (optionally row-weighted) --
__global__ void colsum_k(const float* __restrict__ src, const float* __restrict__ wmask,
                         float* __restrict__ dst)
{
    const int b = blockIdx.x, c = blockIdx.y * 128 + threadIdx.x;
    const float* S = src + (size_t)b * L_ * L_;
    float acc = 0.f;
#pragma unroll 4
    for (int r = 0; r < L_; r++) {
        float w = wmask ? wmask[b * L_ + r] : 1.f;
        acc = fmaf(S[(size_t)r * L_ + c], w, acc);
    }
    dst[b * L_ + c] = acc;
}

// ---------------- A1 (row-softmask) + A2 (col-softmask, transposed) ----
__global__ void a12_k(const float* __restrict__ mask)
{
    __shared__ float s[32][33];
    const int b = blockIdx.z;
    const int i0 = blockIdx.y * 32, j0 = blockIdx.x * 32;
    const int tx = threadIdx.x, ty = threadIdx.y;
    const float* Eb = g_G + (size_t)b * L_ * L_;
    const float* mk = mask + b * L_;
    s[ty][tx] = Eb[(size_t)(i0 + ty) * L_ + j0 + tx];
    __syncthreads();
    float a1 = s[ty][tx] * mk[j0 + tx] / (g_rowsum[b * L_ + i0 + ty] + EPSF) * mk[i0 + ty];
    g_A1[(size_t)b * L_ * L_ + (size_t)(i0 + ty) * L_ + j0 + tx] = a1;
    // A2[p,q] = expG[q,p]*mask[q]/(colsum[p]+eps)*mask[p] with p=j0+ty, q=i0+tx
    float a2 = s[tx][ty] * mk[i0 + tx] / (g_colsum[b * L_ + j0 + ty] + EPSF) * mk[j0 + ty];
    g_A2[(size_t)b * L_ * L_ + (size_t)(j0 + ty) * L_ + i0 + tx] = a2;
}

// ---------------- dense [D]->3 head (+ optional confidence) -----------
__global__ void pred3_k(const float* __restrict__ X, int D,
                        const float* __restrict__ Wd, const float* __restrict__ bd,
                        float* __restrict__ out, float* __restrict__ conf)
{
    const int m = blockIdx.x, t = threadIdx.x;   // 128 threads
    const float* xr = X + (size_t)m * D;
    float a0 = 0.f, a1 = 0.f, a2 = 0.f;
    for (int k = t; k < D; k += 128) {
        float x = xr[k];
        a0 = fmaf(x, Wd[3 * k + 0], a0);
        a1 = fmaf(x, Wd[3 * k + 1], a1);
        a2 = fmaf(x, Wd[3 * k + 2], a2);
    }
#pragma unroll
    for (int o = 16; o > 0; o >>= 1) {
        a0 += __shfl_down_sync(0xffffffffu, a0, o);
        a1 += __shfl_down_sync(0xffffffffu, a1, o);
        a2 += __shfl_down_sync(0xffffffffu, a2, o);
    }
    __shared__ float sh[4][3];
    const int w = t >> 5, ln = t & 31;
    if (ln == 0) { sh[w][0] = a0; sh[w][1] = a1; sh[w][2] = a2; }
    __syncthreads();
    if (t == 0) {
        float p0 = sh[0][0] + sh[1][0] + sh[2][0] + sh[3][0] + bd[0];
        float p1 = sh[0][1] + sh[1][1] + sh[2][1] + sh[3][1] + bd[1];
        float p2 = sh[0][2] + sh[1][2] + sh[2][2] + sh[3][2] + bd[2];
        out[(size_t)m * 3 + 0] = p0;
        out[(size_t)m * 3 + 1] = p1;
        out[(size_t)m * 3 + 2] = p2;
        if (conf) {
            float mx = fmaxf(p0, fmaxf(p1, p2));
            float e0 = expf(p0 - mx), e1 = expf(p1 - mx), e2 = expf(p2 - mx);
            conf[m] = fmaxf(0.f, 1.f - 2.f * e0 / (e0 + e1 + e2));
        }
    }
}

// ---------------- per-batch mask sums ----------------
__global__ void msum_k(const float* __restrict__ mask)
{
    const int b = blockIdx.x, t = threadIdx.x;   // 512 threads
    __shared__ float red[512];
    red[t] = mask[b * L_ + t]; __syncthreads();
    for (int st = 256; st > 0; st >>= 1) { if (t < st) red[t] += red[t + st]; __syncthreads(); }
    if (t == 0) g_msum[b] = red[0];
}

// ---- softmask(WS, scale=True) + A1 + conf*msum*colsumP, in place ------
__global__ void smax_combine_k(const float* __restrict__ mask)
{
    const int row = blockIdx.x, t = threadIdx.x;  // 512 threads
    const int b = row >> 9, i = row & 511;
    const size_t base = (size_t)row * L_;
    float v = g_A2[base + t];
    __shared__ float red[512];
    red[t] = v; __syncthreads();
    for (int st = 256; st > 0; st >>= 1) { if (t < st) red[t] = fmaxf(red[t], red[t + st]); __syncthreads(); }
    const float mx = red[0]; __syncthreads();
    float e = expf(v - mx) * mask[b * L_ + t];
    red[t] = e; __syncthreads();
    for (int st = 256; st > 0; st >>= 1) { if (t < st) red[t] += red[t + st]; __syncthreads(); }
    const float sum = red[0];
    float att = e / (sum + EPSF) * mask[b * L_ + i];
    g_A2[base + t] = att + g_A1[base + t] + g_conf[row] * g_msum[b] * g_colsumP[b * L_ + t];
}

// =====================================================================
extern "C" void kernel_launch(void* const* d_in, const int* in_sizes, int n_in,
                              void* d_out, int out_size)
{
    const float* aspect_in  = (const float*)d_in[0];
    const float* opinion_in = (const float*)d_in[1];
    const float* context_in = (const float*)d_in[2];
    const float* cq         = (const float*)d_in[3];
    const float* mask       = (const float*)d_in[4];
    const float* pos        = (const float*)d_in[5];
    const float* Wa  = (const float*)d_in[6];
    const float* ba  = (const float*)d_in[7];
    const float* Wo  = (const float*)d_in[8];
    const float* bo  = (const float*)d_in[9];
    const float* Wc  = (const float*)d_in[10];
    const float* bc  = (const float*)d_in[11];
    const float* Wda = (const float*)d_in[12];
    const float* bda = (const float*)d_in[13];
    const float* Wdo = (const float*)d_in[14];
    const float* bdo = (const float*)d_in[15];
    const float* Wds = (const float*)d_in[16];
    const float* bds = (const float*)d_in[17];
    float* out = (float*)d_out;

    float *aconv, *oconv, *G, *A1, *A2, *inva, *invo, *invc, *colsumP, *conf;
    cudaGetSymbolAddress((void**)&aconv,   g_aconv);
    cudaGetSymbolAddress((void**)&oconv,   g_oconv);
    cudaGetSymbolAddress((void**)&G,       g_G);
    cudaGetSymbolAddress((void**)&A1,      g_A1);
    cudaGetSymbolAddress((void**)&A2,      g_A2);
    cudaGetSymbolAddress((void**)&inva,    g_inva);
    cudaGetSymbolAddress((void**)&invo,    g_invo);
    cudaGetSymbolAddress((void**)&invc,    g_invc);
    cudaGetSymbolAddress((void**)&colsumP, g_colsumP);
    cudaGetSymbolAddress((void**)&conf,    g_conf);
    float* colsum; cudaGetSymbolAddress((void**)&colsum, g_colsum);

    // ---- convolutions (write conv halves of interacts / context_conv) ----
    conv_gemm<<<dim3(128, 4), 256>>>(aspect_in,  Wa, ba, aconv, F_, out + OFF_AINT, 1024, F_);
    conv_gemm<<<dim3(128, 4), 256>>>(opinion_in, Wo, bo, oconv, F_, out + OFF_OINT, 1024, F_);
    conv_gemm<<<dim3(128, 6), 256>>>(context_in, Wc, bc, out + OFF_CCONV, E_, nullptr, 0, E_);

    // ---- inverse l2 norms ----
    rowinv_k<<<M_, 256>>>(aconv, F_, inva);
    rowinv_k<<<M_, 256>>>(oconv, F_, invo);
    rowinv_k<<<M_, 256>>>(out + OFF_CCONV, E_, invc);

    // ---- gram + bidirectional softmasks ----
    gemm_nt<<<dim3(4, 4, B_), 256>>>(aconv, oconv, G, inva, invo, F_);
    exp_rowsum_k<<<M_, 512>>>(mask);
    colsum_k<<<dim3(B_, 4), 128>>>(G, mask, colsum);
    a12_k<<<dim3(16, 16, B_), dim3(32, 32)>>>(mask);

    // ---- attention-weighted halves of interacts ----
    gemm_nn<<<dim3(4, 4, B_), 256>>>(A1, oconv, out + OFF_AINT + 512, nullptr, 512, 512, 1024);
    gemm_nn<<<dim3(4, 4, B_), 256>>>(A2, aconv, out + OFF_OINT + 512, nullptr, 512, 512, 1024);

    // ---- prediction heads + opinion confidence ----
    pred3_k<<<M_, 128>>>(out + OFF_AINT, 1024, Wda, bda, out + OFF_APRED, nullptr);
    pred3_k<<<M_, 128>>>(out + OFF_OINT, 1024, Wdo, bdo, out + OFF_OPRED, conf);

    // ---- collapsed opinion propagation terms ----
    colsum_k<<<dim3(B_, 4), 128>>>(pos, nullptr, colsumP);
    msum_k<<<B_, 512>>>(mask);

    // ---- context attention ----
    gemm_nt<<<dim3(4, 4, B_), 256>>>(cq, out + OFF_CCONV, G, nullptr, invc, E_);   // WS0 -> G
    gemm_nn<<<dim3(4, 4, B_), 256>>>(G, pos, A2, nullptr, 512, 512, 512);          // WS  -> A2
    smax_combine_k<<<M_, 512>>>(mask);                                             // word_attend -> A2
    gemm_nn<<<dim3(4, 6, B_), 256>>>(A2, out + OFF_CCONV, out + OFF_CINT, cq, 512, E_, E_);
    pred3_k<<<M_, 128>>>(out + OFF_CINT, E_, Wds, bds, out + OFF_SPRED, nullptr);
}